// round 14
// baseline (speedup 1.0000x reference)
#include <cuda_runtime.h>
#include <cstdint>

// ---------------------------------------------------------------------------
// MetaMLP (3-step GraphNet) on GB300 — mma.sync everywhere; tig-pair float4
// epilogues; LDG.128+xor-1 edge A-path; 256-edge edge tiles (B-LDS halved);
// uWn3b folded into global_kernel.
// ---------------------------------------------------------------------------

#define D 128
static constexpr int N_NODES  = 50000;
static constexpr int N_EDGES  = 800000;
static constexpr int N_GRAPHS = 16;
static constexpr int OUTW     = 4 * D;           // 512 output cols per row
static constexpr int N_ETILES = N_EDGES / 256;   // 3125 (256-edge tiles)
static constexpr int N_RTILES = (N_NODES + 127) / 128;  // 391

typedef unsigned long long u64;

// ------------------------- device scratch (no allocs) ----------------------
__device__ float g_ea  [(size_t)N_EDGES  * D];
__device__ float g_P12 [(size_t)N_NODES  * 2 * D];   // [P1+uW4b+b | P2]
__device__ float g_agg [(size_t)N_NODES  * D];
__device__ float g_u    [N_GRAPHS * D];
__device__ float g_uWn3b[N_GRAPHS * D];
__device__ float g_gsum [N_GRAPHS * D];
__device__ float g_invN [N_NODES];
__device__ float g_invG [N_GRAPHS];

// ------------------------------ helpers ------------------------------------
__device__ __forceinline__ uint32_t cvt_bf16x2(float a, float b) {
    uint32_t r;
    asm("cvt.rn.bf16x2.f32 %0, %1, %2;" : "=r"(r) : "f"(b), "f"(a));
    return r;
}
__device__ __forceinline__ void split2(float x, float y, uint32_t& hi, uint32_t& lo) {
    hi = cvt_bf16x2(x, y);
    float hx = __uint_as_float(hi << 16);
    float hy = __uint_as_float(hi & 0xffff0000u);
    lo = cvt_bf16x2(x - hx, y - hy);
}
__device__ __forceinline__ void mma_bf16(float* d, const uint32_t* a, uint32_t b0, uint32_t b1) {
    asm volatile("mma.sync.aligned.m16n8k16.row.col.f32.bf16.bf16.f32 "
        "{%0,%1,%2,%3}, {%4,%5,%6,%7}, {%8,%9}, {%0,%1,%2,%3};"
        : "+f"(d[0]), "+f"(d[1]), "+f"(d[2]), "+f"(d[3])
        : "r"(a[0]), "r"(a[1]), "r"(a[2]), "r"(a[3]), "r"(b0), "r"(b1));
}
__device__ __forceinline__ void red_add4(float* addr, float4 v) {
    asm volatile("red.global.add.v4.f32 [%0], {%1, %2, %3, %4};"
                 :: "l"(addr), "f"(v.x), "f"(v.y), "f"(v.z), "f"(v.w) : "memory");
}

// tig-pair combine: even tig returns nt0's float4, odd tig returns nt1's.
__device__ __forceinline__ float4 pair_combine(float a0, float a1, float b0, float b1,
                                               bool even) {
    float sa0 = __shfl_xor_sync(0xffffffffu, a0, 1);
    float sa1 = __shfl_xor_sync(0xffffffffu, a1, 1);
    float sb0 = __shfl_xor_sync(0xffffffffu, b0, 1);
    float sb1 = __shfl_xor_sync(0xffffffffu, b1, 1);
    return even ? make_float4(a0, a1, sa0, sa1) : make_float4(sb0, sb1, b0, b1);
}

// widened A-fragment build: lane loaded float4 at col (tig&1)*8+(tig>>1)*4.
__device__ __forceinline__ void frag_from_f4(float4 f, bool even,
                                             uint32_t& rlo_h, uint32_t& rlo_l,
                                             uint32_t& rhi_h, uint32_t& rhi_l) {
    uint32_t h01, l01, h23, l23;
    split2(f.x, f.y, h01, l01);
    split2(f.z, f.w, h23, l23);
    uint32_t sh01 = __shfl_xor_sync(0xffffffffu, h01, 1);
    uint32_t sl01 = __shfl_xor_sync(0xffffffffu, l01, 1);
    uint32_t sh23 = __shfl_xor_sync(0xffffffffu, h23, 1);
    uint32_t sl23 = __shfl_xor_sync(0xffffffffu, l23, 1);
    rlo_h = even ? h01 : sh23;
    rlo_l = even ? l01 : sl23;
    rhi_h = even ? sh01 : h23;
    rhi_l = even ? sl01 : l23;
}

// ------------------------------ init (launch 0) -----------------------------
__global__ void init_kernel(const float* __restrict__ x, const float* __restrict__ u,
                            float* __restrict__ out_x, float* __restrict__ out_g) {
    int stride = gridDim.x * blockDim.x;
    int tid0 = blockIdx.x * blockDim.x + threadIdx.x;
    for (int i = tid0; i < N_NODES * D; i += stride) {
        int r = i >> 7, c = i & (D - 1);
        out_x[(size_t)r * OUTW + c] = x[i];
        g_agg[i] = 0.f;
    }
    for (int i = tid0; i < N_GRAPHS * D; i += stride) {
        int r = i >> 7, c = i & (D - 1);
        out_g[(size_t)r * OUTW + c] = u[i];
        g_u[i] = u[i];
    }
    for (int i = tid0; i < N_NODES; i += stride) g_invN[i] = 0.f;
    for (int i = tid0; i < N_GRAPHS; i += stride) g_invG[i] = 0.f;
}

// ------------------------------ hist / finalize ------------------------------
__global__ void hist_kernel(const int* __restrict__ dst, const int* __restrict__ batch) {
    int stride = gridDim.x * blockDim.x;
    int tid0 = blockIdx.x * blockDim.x + threadIdx.x;
    for (int i = tid0; i < N_EDGES; i += stride) atomicAdd(&g_invN[dst[i]], 1.f);
    for (int i = tid0; i < N_NODES; i += stride) atomicAdd(&g_invG[batch[i]], 1.f);
}

__global__ void finalize_counts_kernel() {
    int stride = gridDim.x * blockDim.x;
    int tid0 = blockIdx.x * blockDim.x + threadIdx.x;
    for (int i = tid0; i < N_NODES; i += stride) g_invN[i] = 1.f / fmaxf(g_invN[i], 1.f);
    for (int i = tid0; i < N_GRAPHS; i += stride) g_invG[i] = 1.f / fmaxf(g_invG[i], 1.f);
}

// -------------------- uWn3b precompute (initial step only) ------------------
__global__ void prep_uwn3_kernel(const float* __restrict__ W_node,
                                 const float* __restrict__ b_node) {
    int g = blockIdx.x, j = threadIdx.x;
    __shared__ float su[D];
    su[j] = g_u[g * D + j];
    __syncthreads();
    const float* W3 = W_node + 2 * D * D;
    float acc = b_node[j];
#pragma unroll 8
    for (int k = 0; k < D; k++) acc = fmaf(su[k], W3[k * D + j], acc);
    g_uWn3b[g * D + j] = acc;
}

// ----------------------- matvec P1/P2 (mma.sync, 512 thr) -------------------
__global__ void __launch_bounds__(512, 1) matvec_mma_kernel(
    const float* __restrict__ Xin, const float* __restrict__ W_edge,
    const float* __restrict__ b_edge, const int* __restrict__ batch) {
    extern __shared__ char smemraw[];
    uint4* sB  = (uint4*)smemraw;                 // [nt32][ks8][lane32] 128 KB
    float* sGu = (float*)(smemraw + 131072);      // 8 KB
    float* sUW = (float*)(smemraw + 139264);      // 8 KB
    int tid = threadIdx.x;

    for (int i = tid; i < 32 * 8 * 32; i += 512) {
        int lane = i & 31, ks = (i >> 5) & 7, nt = i >> 8;
        int gidw = lane >> 2, tigw = lane & 3;
        int n  = nt * 8 + gidw;
        int k0 = ks * 16 + tigw * 2;
        const float* W = (n < D) ? (W_edge + n) : (W_edge + D * D + (n - D));
        float w00 = __ldg(W + k0 * D);
        float w01 = __ldg(W + (k0 + 1) * D);
        float w10 = __ldg(W + (k0 + 8) * D);
        float w11 = __ldg(W + (k0 + 9) * D);
        uint32_t b0h, b0l, b1h, b1l;
        split2(w00, w01, b0h, b0l);
        split2(w10, w11, b1h, b1l);
        sB[i] = make_uint4(b0h, b1h, b0l, b1l);
    }
    for (int i = tid; i < N_GRAPHS * D; i += 512) sGu[i] = g_u[i];
    __syncthreads();
    {
        int j = tid & 127, q4 = tid >> 7;
        float acc[4];
#pragma unroll
        for (int q = 0; q < 4; q++) acc[q] = 0.f;
        const float* W4 = W_edge + 3 * D * D;
        for (int k = 0; k < D; k++) {
            float w = __ldg(W4 + k * D + j);
#pragma unroll
            for (int q = 0; q < 4; q++)
                acc[q] = fmaf(sGu[(q4 * 4 + q) * D + k], w, acc[q]);
        }
        float bj = __ldg(b_edge + j);
#pragma unroll
        for (int q = 0; q < 4; q++) sUW[(q4 * 4 + q) * D + j] = acc[q] + bj;
    }
    __syncthreads();

    int wid = tid >> 5, lane = tid & 31;
    int gid = lane >> 2, tig = lane & 3;
    int wm = wid & 3, wn = wid >> 2;
    bool even = ((tig & 1) == 0);

    for (int tile = blockIdx.x; tile < N_RTILES; tile += gridDim.x) {
        int rbase = tile * 128 + wm * 32;
        float acc[2][8][4];
#pragma unroll
        for (int mt = 0; mt < 2; mt++)
#pragma unroll
            for (int nt = 0; nt < 8; nt++)
#pragma unroll
                for (int q = 0; q < 4; q++) acc[mt][nt][q] = 0.f;

        const float* pA[2];
        const float* pA8[2];
#pragma unroll
        for (int mt = 0; mt < 2; mt++) {
            int r0 = rbase + mt * 16 + gid;
            if (r0 > N_NODES - 1) r0 = N_NODES - 1;
            pA[mt] = Xin + (size_t)r0 * OUTW + tig * 2;
            int r1 = rbase + mt * 16 + 8 + gid;
            if (r1 > N_NODES - 1) r1 = N_NODES - 1;
            pA8[mt] = Xin + (size_t)r1 * OUTW + tig * 2;
        }

#pragma unroll
        for (int ks = 0; ks < 8; ks++) {
            uint32_t ah[2][4], al[2][4];
#pragma unroll
            for (int mt = 0; mt < 2; mt++) {
                float2 v0 = __ldg((const float2*)(pA[mt]  + ks * 16));
                float2 v1 = __ldg((const float2*)(pA8[mt] + ks * 16));
                float2 v2 = __ldg((const float2*)(pA[mt]  + ks * 16 + 8));
                float2 v3 = __ldg((const float2*)(pA8[mt] + ks * 16 + 8));
                split2(v0.x, v0.y, ah[mt][0], al[mt][0]);
                split2(v1.x, v1.y, ah[mt][1], al[mt][1]);
                split2(v2.x, v2.y, ah[mt][2], al[mt][2]);
                split2(v3.x, v3.y, ah[mt][3], al[mt][3]);
            }
#pragma unroll
            for (int nt = 0; nt < 8; nt++) {
                uint4 b = sB[((wn * 8 + nt) * 8 + ks) * 32 + lane];
#pragma unroll
                for (int mt = 0; mt < 2; mt++) {
                    mma_bf16(acc[mt][nt], ah[mt], b.x, b.y);
                    mma_bf16(acc[mt][nt], ah[mt], b.z, b.w);
                    mma_bf16(acc[mt][nt], al[mt], b.x, b.y);
                }
            }
        }

#pragma unroll
        for (int mt = 0; mt < 2; mt++) {
#pragma unroll
            for (int h = 0; h < 2; h++) {
                int row = rbase + mt * 16 + h * 8 + gid;
                bool ok = row < N_NODES;
                int g = __ldg(batch + (ok ? row : N_NODES - 1));
                float* base = g_P12 + (size_t)row * 256;
#pragma unroll
                for (int np = 0; np < 4; np++) {
                    int nt0 = 2 * np, nt1 = 2 * np + 1;
                    float4 v = pair_combine(acc[mt][nt0][h * 2], acc[mt][nt0][h * 2 + 1],
                                            acc[mt][nt1][h * 2], acc[mt][nt1][h * 2 + 1],
                                            even);
                    int n = wn * 64 + (even ? nt0 : nt1) * 8 + (tig & 2) * 2;
                    if (ok) {
                        if (n < D) {
                            float4 uv = *(float4*)(sUW + g * D + n);
                            v.x += uv.x; v.y += uv.y; v.z += uv.z; v.w += uv.w;
                        }
                        *(float4*)(base + n) = v;
                    }
                }
            }
        }
    }
}

// ------------------------- edge kernel: mma.sync ----------------------------
// 256-edge tiles, 512 threads (16 warps = 8 m-slices x 2 n-halves).
// ea' = relu(ea@We3 + P1'[src] + P2[dst]); red.v4 to agg.
__global__ void __launch_bounds__(512, 1) edge_mma_kernel(
    int step0, int store_ea, const float* __restrict__ ext_ea,
    const int* __restrict__ src, const int* __restrict__ dst,
    const float* __restrict__ We3) {
    extern __shared__ uint4 sBe[];   // [nt=16][ks=8][lane=32]
    int tid = threadIdx.x;

    for (int i = tid; i < 16 * 8 * 32; i += 512) {
        int lane = i & 31, ks = (i >> 5) & 7, nt = i >> 8;
        int gidw = lane >> 2, tigw = lane & 3;
        int n  = nt * 8 + gidw;
        int k0 = ks * 16 + tigw * 2;
        float w00 = __ldg(We3 + k0 * D + n);
        float w01 = __ldg(We3 + (k0 + 1) * D + n);
        float w10 = __ldg(We3 + (k0 + 8) * D + n);
        float w11 = __ldg(We3 + (k0 + 9) * D + n);
        uint32_t b0h, b0l, b1h, b1l;
        split2(w00, w01, b0h, b0l);
        split2(w10, w11, b1h, b1l);
        sBe[i] = make_uint4(b0h, b1h, b0l, b1l);
    }
    __syncthreads();

    int wid = tid >> 5, lane = tid & 31;
    int gid = lane >> 2, tig = lane & 3;
    int wm = wid & 7, wn = wid >> 3;
    bool even = ((tig & 1) == 0);
    int colo = ((tig & 1) << 3) + ((tig >> 1) << 2);   // (tig&1)*8 + (tig>>1)*4
    const float* ea_in = step0 ? ext_ea : (const float*)g_ea;

    for (int tile = blockIdx.x; tile < N_ETILES; tile += gridDim.x) {
        const float* A = ea_in + (size_t)tile * (256 * 128);
        const float* base0 = A + (wm * 32 + 0 * 16 + gid) * 128 + colo;
        const float* base1 = A + (wm * 32 + 1 * 16 + gid) * 128 + colo;

        int sidx[2][2], didx[2][2];
#pragma unroll
        for (int mt = 0; mt < 2; mt++)
#pragma unroll
            for (int h = 0; h < 2; h++) {
                int r = tile * 256 + wm * 32 + mt * 16 + h * 8 + gid;
                sidx[mt][h] = __ldg(src + r);
                didx[mt][h] = __ldg(dst + r);
            }

        float acc[2][8][4];
#pragma unroll
        for (int mt = 0; mt < 2; mt++)
#pragma unroll
            for (int nt = 0; nt < 8; nt++)
#pragma unroll
                for (int q = 0; q < 4; q++) acc[mt][nt][q] = 0.f;

        float4 cur[2][2], nxt[2][2];
#pragma unroll
        for (int mt = 0; mt < 2; mt++) {
            const float* b = mt ? base1 : base0;
            cur[mt][0] = __ldg((const float4*)b);
            cur[mt][1] = __ldg((const float4*)(b + 8 * 128));
        }
#pragma unroll
        for (int ks = 0; ks < 8; ks++) {
            if (ks < 7) {
#pragma unroll
                for (int mt = 0; mt < 2; mt++) {
                    const float* b = (mt ? base1 : base0) + (ks + 1) * 16;
                    nxt[mt][0] = __ldg((const float4*)b);
                    nxt[mt][1] = __ldg((const float4*)(b + 8 * 128));
                }
            }
            uint32_t ah[2][4], al[2][4];
#pragma unroll
            for (int mt = 0; mt < 2; mt++) {
                frag_from_f4(cur[mt][0], even, ah[mt][0], al[mt][0], ah[mt][2], al[mt][2]);
                frag_from_f4(cur[mt][1], even, ah[mt][1], al[mt][1], ah[mt][3], al[mt][3]);
            }
#pragma unroll
            for (int nt = 0; nt < 8; nt++) {
                uint4 b = sBe[((wn * 8 + nt) * 8 + ks) * 32 + lane];
#pragma unroll
                for (int mt = 0; mt < 2; mt++) {
                    mma_bf16(acc[mt][nt], ah[mt], b.x, b.y);
                    mma_bf16(acc[mt][nt], ah[mt], b.z, b.w);
                    mma_bf16(acc[mt][nt], al[mt], b.x, b.y);
                }
            }
#pragma unroll
            for (int mt = 0; mt < 2; mt++) {
                cur[mt][0] = nxt[mt][0];
                cur[mt][1] = nxt[mt][1];
            }
        }

        // tig-pair float4 epilogue
#pragma unroll
        for (int mt = 0; mt < 2; mt++) {
#pragma unroll
            for (int h = 0; h < 2; h++) {
                int r = tile * 256 + wm * 32 + mt * 16 + h * 8 + gid;
                int s = sidx[mt][h], d = didx[mt][h];
                const float* p1b = g_P12 + (size_t)s * 256;
                const float* p2b = g_P12 + (size_t)d * 256 + 128;
                float* eo = g_ea + (size_t)r * D;
                float* ao = g_agg + (size_t)d * D;
#pragma unroll
                for (int np = 0; np < 4; np++) {
                    int nt0 = 2 * np, nt1 = 2 * np + 1;
                    float4 v = pair_combine(acc[mt][nt0][h * 2], acc[mt][nt0][h * 2 + 1],
                                            acc[mt][nt1][h * 2], acc[mt][nt1][h * 2 + 1],
                                            even);
                    int c = wn * 64 + (even ? nt0 : nt1) * 8 + (tig & 2) * 2;
                    float4 p1 = __ldg((const float4*)(p1b + c));
                    float4 p2 = __ldg((const float4*)(p2b + c));
                    float4 rr;
                    rr.x = fmaxf(v.x + p1.x + p2.x, 0.f);
                    rr.y = fmaxf(v.y + p1.y + p2.y, 0.f);
                    rr.z = fmaxf(v.z + p1.z + p2.z, 0.f);
                    rr.w = fmaxf(v.w + p1.w + p2.w, 0.f);
                    if (store_ea) *(float4*)(eo + c) = rr;
                    red_add4(ao + c, rr);
                }
            }
        }
    }
}

// ------------------------- node kernel (mma.sync, 512 thr) ------------------
__global__ void __launch_bounds__(512, 1) node_mma_kernel(
    const float* __restrict__ Xin, float* __restrict__ Xout,
    const int* __restrict__ batch, const float* __restrict__ W_node) {
    extern __shared__ char smemraw[];
    uint4* sB = (uint4*)smemraw;                  // [nt16][ks16][lane32] 128 KB
    float* sU = (float*)(smemraw + 131072);       // 8 KB
    int tid = threadIdx.x;

    for (int i = tid; i < 16 * 16 * 32; i += 512) {
        int lane = i & 31, ks = (i >> 5) & 15, nt = i >> 9;
        int gidw = lane >> 2, tigw = lane & 3;
        int n  = nt * 8 + gidw;
        int k0 = ks * 16 + tigw * 2;
        float w00 = __ldg(W_node + k0 * D + n);
        float w01 = __ldg(W_node + (k0 + 1) * D + n);
        float w10 = __ldg(W_node + (k0 + 8) * D + n);
        float w11 = __ldg(W_node + (k0 + 9) * D + n);
        uint32_t b0h, b0l, b1h, b1l;
        split2(w00, w01, b0h, b0l);
        split2(w10, w11, b1h, b1l);
        sB[i] = make_uint4(b0h, b1h, b0l, b1l);
    }
    for (int i = tid; i < N_GRAPHS * D; i += 512) sU[i] = g_uWn3b[i];
    __syncthreads();

    int wid = tid >> 5, lane = tid & 31;
    int gid = lane >> 2, tig = lane & 3;
    int wm = wid & 3, wn = wid >> 2;
    bool even = ((tig & 1) == 0);

    for (int tile = blockIdx.x; tile < N_RTILES; tile += gridDim.x) {
        int rbase = tile * 128 + wm * 32;
        int r0c[2], r1c[2];
        float inv0[2], inv1[2];
#pragma unroll
        for (int mt = 0; mt < 2; mt++) {
            int r0 = rbase + mt * 16 + gid;      if (r0 > N_NODES - 1) r0 = N_NODES - 1;
            int r1 = rbase + mt * 16 + 8 + gid;  if (r1 > N_NODES - 1) r1 = N_NODES - 1;
            r0c[mt] = r0; r1c[mt] = r1;
            inv0[mt] = __ldg(&g_invN[r0]);
            inv1[mt] = __ldg(&g_invN[r1]);
        }

        float acc[2][4][4];
#pragma unroll
        for (int mt = 0; mt < 2; mt++)
#pragma unroll
            for (int nt = 0; nt < 4; nt++)
#pragma unroll
                for (int q = 0; q < 4; q++) acc[mt][nt][q] = 0.f;

#pragma unroll
        for (int ks = 0; ks < 16; ks++) {
            uint32_t ah[2][4], al[2][4];
#pragma unroll
            for (int mt = 0; mt < 2; mt++) {
                float2 v0, v1, v2, v3;
                if (ks < 8) {
                    const float* p0 = Xin + (size_t)r0c[mt] * OUTW + ks * 16 + tig * 2;
                    const float* p1 = Xin + (size_t)r1c[mt] * OUTW + ks * 16 + tig * 2;
                    v0 = __ldg((const float2*)p0);
                    v1 = __ldg((const float2*)p1);
                    v2 = __ldg((const float2*)(p0 + 8));
                    v3 = __ldg((const float2*)(p1 + 8));
                } else {
                    const float* p0 = g_agg + (size_t)r0c[mt] * D + (ks - 8) * 16 + tig * 2;
                    const float* p1 = g_agg + (size_t)r1c[mt] * D + (ks - 8) * 16 + tig * 2;
                    v0 = __ldg((const float2*)p0);
                    v1 = __ldg((const float2*)p1);
                    v2 = __ldg((const float2*)(p0 + 8));
                    v3 = __ldg((const float2*)(p1 + 8));
                    v0.x *= inv0[mt]; v0.y *= inv0[mt];
                    v1.x *= inv1[mt]; v1.y *= inv1[mt];
                    v2.x *= inv0[mt]; v2.y *= inv0[mt];
                    v3.x *= inv1[mt]; v3.y *= inv1[mt];
                }
                split2(v0.x, v0.y, ah[mt][0], al[mt][0]);
                split2(v1.x, v1.y, ah[mt][1], al[mt][1]);
                split2(v2.x, v2.y, ah[mt][2], al[mt][2]);
                split2(v3.x, v3.y, ah[mt][3], al[mt][3]);
            }
#pragma unroll
            for (int nt = 0; nt < 4; nt++) {
                uint4 b = sB[((wn * 4 + nt) * 16 + ks) * 32 + lane];
#pragma unroll
                for (int mt = 0; mt < 2; mt++) {
                    mma_bf16(acc[mt][nt], ah[mt], b.x, b.y);
                    mma_bf16(acc[mt][nt], ah[mt], b.z, b.w);
                    mma_bf16(acc[mt][nt], al[mt], b.x, b.y);
                }
            }
        }

        // all agg reads of this tile done before epilogue zeroes agg rows
        __syncthreads();

        // tig-pair float4 epilogue: Xout rows + red.v4 + agg zeroing
#pragma unroll
        for (int mt = 0; mt < 2; mt++) {
#pragma unroll
            for (int h = 0; h < 2; h++) {
                int row = rbase + mt * 16 + h * 8 + gid;
                bool ok = row < N_NODES;
                int g = __ldg(batch + (ok ? row : N_NODES - 1));
                float* xo = Xout + (size_t)row * OUTW;
                float* ag = g_agg + (size_t)row * D;
#pragma unroll
                for (int np = 0; np < 2; np++) {
                    int nt0 = 2 * np, nt1 = 2 * np + 1;
                    float4 v = pair_combine(acc[mt][nt0][h * 2], acc[mt][nt0][h * 2 + 1],
                                            acc[mt][nt1][h * 2], acc[mt][nt1][h * 2 + 1],
                                            even);
                    int c = wn * 32 + (even ? nt0 : nt1) * 8 + (tig & 2) * 2;
                    if (ok) {
                        float4 uv = *(float4*)(sU + g * D + c);
                        float4 rr;
                        rr.x = fmaxf(v.x + uv.x, 0.f);
                        rr.y = fmaxf(v.y + uv.y, 0.f);
                        rr.z = fmaxf(v.z + uv.z, 0.f);
                        rr.w = fmaxf(v.w + uv.w, 0.f);
                        *(float4*)(xo + c) = rr;
                        red_add4(g_gsum + g * D + c, rr);
                        *(float4*)(ag + c) = make_float4(0.f, 0.f, 0.f, 0.f);
                    }
                }
            }
        }
    }
}

// -------------------- global kernel (+ next-step uWn3b) ----------------------
__global__ void global_kernel(const float* __restrict__ W_glob,
                              const float* __restrict__ b_glob,
                              const float* __restrict__ W_node,
                              const float* __restrict__ b_node,
                              float* __restrict__ out_g) {
    int g = blockIdx.x;
    int j = threadIdx.x;
    __shared__ float su[D], sm[D], snu[D];
    su[j] = g_u[g * D + j];
    sm[j] = g_gsum[g * D + j] * g_invG[g];
    g_gsum[g * D + j] = 0.f;
    __syncthreads();
    float acc = b_glob[j];
#pragma unroll 4
    for (int k = 0; k < D; k++) acc = fmaf(su[k], W_glob[k * D + j], acc);
#pragma unroll 4
    for (int k = 0; k < D; k++) acc = fmaf(sm[k], W_glob[(D + k) * D + j], acc);
    float r = fmaxf(acc, 0.f);
    out_g[(size_t)g * OUTW + j] = r;
    g_u[g * D + j] = r;
    snu[j] = r;
    __syncthreads();
    // uWn3b for the NEXT step from the new u
    const float* W3 = W_node + 2 * D * D;
    float a2 = b_node[j];
#pragma unroll 8
    for (int k = 0; k < D; k++) a2 = fmaf(snu[k], W3[k * D + j], a2);
    g_uWn3b[g * D + j] = a2;
}

// --------------------------------- launch ----------------------------------
extern "C" void kernel_launch(void* const* d_in, const int* in_sizes, int n_in,
                              void* d_out, int out_size) {
    const float* x      = (const float*)d_in[0];
    const int*   ei     = (const int*)d_in[1];
    const float* ea     = (const float*)d_in[2];
    const float* u      = (const float*)d_in[3];
    const int*   batch  = (const int*)d_in[4];
    const float* W_edge = (const float*)d_in[5];
    const float* b_edge = (const float*)d_in[6];
    const float* W_node = (const float*)d_in[7];
    const float* b_node = (const float*)d_in[8];
    const float* W_glob = (const float*)d_in[9];
    const float* b_glob = (const float*)d_in[10];

    const int* src = ei;
    const int* dstp = ei + N_EDGES;

    float* out   = (float*)d_out;
    float* out_x = out;                            // 50000 x 512
    float* out_g = out + (size_t)N_NODES * OUTW;   // 16 x 512

    const int MV_SMEM   = 131072 + 8192 + 8192;    // 147456
    const int EDGE_SMEM = 16 * 8 * 32 * 16;        // 64 KB
    const int NODE_SMEM = 131072 + 8192;           // 139264

    cudaFuncSetAttribute(matvec_mma_kernel, cudaFuncAttributeMaxDynamicSharedMemorySize, MV_SMEM);
    cudaFuncSetAttribute(edge_mma_kernel,   cudaFuncAttributeMaxDynamicSharedMemorySize, EDGE_SMEM);
    cudaFuncSetAttribute(node_mma_kernel,   cudaFuncAttributeMaxDynamicSharedMemorySize, NODE_SMEM);

    // launch order: index 3 (ncu capture point) = edge_mma_kernel
    init_kernel<<<2048, 256>>>(x, u, out_x, out_g);                          // 0
    matvec_mma_kernel<<<148, 512, MV_SMEM>>>(out_x, W_edge, b_edge, batch);  // 1 (t=0)
    hist_kernel<<<1024, 256>>>(dstp, batch);                                 // 2
    edge_mma_kernel<<<148, 512, EDGE_SMEM>>>(1, 1, ea, src, dstp,            // 3 PROFILED
                                             W_edge + 2 * D * D);
    finalize_counts_kernel<<<256, 256>>>();                                  // 4
    prep_uwn3_kernel<<<16, 128>>>(W_node, b_node);                           // 5

    for (int t = 0; t < 3; t++) {
        const float* Xt = out_x + t * D;
        float*       Xn = out_x + (t + 1) * D;

        node_mma_kernel<<<148, 512, NODE_SMEM>>>(Xt, Xn, batch, W_node);
        global_kernel<<<16, 128>>>(W_glob, b_glob, W_node, b_node,
                                   out_g + (t + 1) * D);

        if (t < 2) {
            matvec_mma_kernel<<<148, 512, MV_SMEM>>>(Xn, W_edge, b_edge, batch);
            edge_mma_kernel<<<148, 512, EDGE_SMEM>>>(0, (t + 1) < 2 ? 1 : 0, ea,
                                                     src, dstp, W_edge + 2 * D * D);
        }
    }
}

// round 15
// speedup vs baseline: 1.0348x; 1.0348x over previous
#include <cuda_runtime.h>
#include <cstdint>

// ---------------------------------------------------------------------------
// MetaMLP (3-step GraphNet) on GB300 — R12 configuration (measured best):
// mma.sync everywhere; tig-pair float4 epilogues; LDG.128+xor-1 edge A-path;
// agg/gsum zeroing folded into node/global; vectorized init.
// ---------------------------------------------------------------------------

#define D 128
static constexpr int N_NODES  = 50000;
static constexpr int N_EDGES  = 800000;
static constexpr int N_GRAPHS = 16;
static constexpr int OUTW     = 4 * D;          // 512 output cols per row
static constexpr int N_TILES  = N_EDGES / 128;  // 6250
static constexpr int N_RTILES = (N_NODES + 127) / 128;  // 391

typedef unsigned long long u64;

// ------------------------- device scratch (no allocs) ----------------------
__device__ float g_ea  [(size_t)N_EDGES  * D];
__device__ float g_P12 [(size_t)N_NODES  * 2 * D];   // [P1+uW4b+b | P2]
__device__ float g_agg [(size_t)N_NODES  * D];
__device__ float g_u    [N_GRAPHS * D];
__device__ float g_uWn3b[N_GRAPHS * D];
__device__ float g_gsum [N_GRAPHS * D];
__device__ float g_invN [N_NODES];
__device__ float g_invG [N_GRAPHS];

// ------------------------------ helpers ------------------------------------
__device__ __forceinline__ uint32_t cvt_bf16x2(float a, float b) {
    uint32_t r;
    asm("cvt.rn.bf16x2.f32 %0, %1, %2;" : "=r"(r) : "f"(b), "f"(a));
    return r;
}
__device__ __forceinline__ void split2(float x, float y, uint32_t& hi, uint32_t& lo) {
    hi = cvt_bf16x2(x, y);
    float hx = __uint_as_float(hi << 16);
    float hy = __uint_as_float(hi & 0xffff0000u);
    lo = cvt_bf16x2(x - hx, y - hy);
}
__device__ __forceinline__ void mma_bf16(float* d, const uint32_t* a, uint32_t b0, uint32_t b1) {
    asm volatile("mma.sync.aligned.m16n8k16.row.col.f32.bf16.bf16.f32 "
        "{%0,%1,%2,%3}, {%4,%5,%6,%7}, {%8,%9}, {%0,%1,%2,%3};"
        : "+f"(d[0]), "+f"(d[1]), "+f"(d[2]), "+f"(d[3])
        : "r"(a[0]), "r"(a[1]), "r"(a[2]), "r"(a[3]), "r"(b0), "r"(b1));
}
__device__ __forceinline__ void red_add4(float* addr, float4 v) {
    asm volatile("red.global.add.v4.f32 [%0], {%1, %2, %3, %4};"
                 :: "l"(addr), "f"(v.x), "f"(v.y), "f"(v.z), "f"(v.w) : "memory");
}

// tig-pair combine: even tig returns nt0's float4, odd tig returns nt1's.
__device__ __forceinline__ float4 pair_combine(float a0, float a1, float b0, float b1,
                                               bool even) {
    float sa0 = __shfl_xor_sync(0xffffffffu, a0, 1);
    float sa1 = __shfl_xor_sync(0xffffffffu, a1, 1);
    float sb0 = __shfl_xor_sync(0xffffffffu, b0, 1);
    float sb1 = __shfl_xor_sync(0xffffffffu, b1, 1);
    return even ? make_float4(a0, a1, sa0, sa1) : make_float4(sb0, sb1, b0, b1);
}

// widened A-fragment build: lane loaded float4 at col (tig&1)*8+(tig>>1)*4.
__device__ __forceinline__ void frag_from_f4(float4 f, bool even,
                                             uint32_t& rlo_h, uint32_t& rlo_l,
                                             uint32_t& rhi_h, uint32_t& rhi_l) {
    uint32_t h01, l01, h23, l23;
    split2(f.x, f.y, h01, l01);
    split2(f.z, f.w, h23, l23);
    uint32_t sh01 = __shfl_xor_sync(0xffffffffu, h01, 1);
    uint32_t sl01 = __shfl_xor_sync(0xffffffffu, l01, 1);
    uint32_t sh23 = __shfl_xor_sync(0xffffffffu, h23, 1);
    uint32_t sl23 = __shfl_xor_sync(0xffffffffu, l23, 1);
    rlo_h = even ? h01 : sh23;
    rlo_l = even ? l01 : sl23;
    rhi_h = even ? sh01 : h23;
    rhi_l = even ? sl01 : l23;
}

// ------------------------------ init (launch 0) -----------------------------
// vectorized: float4 copies for x -> out_x and agg zeroing
__global__ void init_kernel(const float* __restrict__ x, const float* __restrict__ u,
                            float* __restrict__ out_x, float* __restrict__ out_g) {
    int stride = gridDim.x * blockDim.x;
    int tid0 = blockIdx.x * blockDim.x + threadIdx.x;
    const int NQ = N_NODES * D / 4;          // 1.6M float4s
    for (int i = tid0; i < NQ; i += stride) {
        int r = i >> 5, c = i & 31;          // 32 float4 per row
        float4 v = __ldg((const float4*)x + i);
        *((float4*)(out_x + (size_t)r * OUTW) + c) = v;
        ((float4*)g_agg)[i] = make_float4(0.f, 0.f, 0.f, 0.f);
    }
    for (int i = tid0; i < N_GRAPHS * D; i += stride) {
        int r = i >> 7, c = i & (D - 1);
        out_g[(size_t)r * OUTW + c] = u[i];
        g_u[i] = u[i];
    }
    for (int i = tid0; i < N_NODES; i += stride) g_invN[i] = 0.f;
    for (int i = tid0; i < N_GRAPHS; i += stride) g_invG[i] = 0.f;
}

// ------------------------------ hist / finalize ------------------------------
__global__ void hist_kernel(const int* __restrict__ dst, const int* __restrict__ batch) {
    int stride = gridDim.x * blockDim.x;
    int tid0 = blockIdx.x * blockDim.x + threadIdx.x;
    for (int i = tid0; i < N_EDGES; i += stride) atomicAdd(&g_invN[dst[i]], 1.f);
    for (int i = tid0; i < N_NODES; i += stride) atomicAdd(&g_invG[batch[i]], 1.f);
}

__global__ void finalize_counts_kernel() {
    int stride = gridDim.x * blockDim.x;
    int tid0 = blockIdx.x * blockDim.x + threadIdx.x;
    for (int i = tid0; i < N_NODES; i += stride) g_invN[i] = 1.f / fmaxf(g_invN[i], 1.f);
    for (int i = tid0; i < N_GRAPHS; i += stride) g_invG[i] = 1.f / fmaxf(g_invG[i], 1.f);
}

// ----------------------- matvec P1/P2 (mma.sync, 512 thr) -------------------
__global__ void __launch_bounds__(512, 1) matvec_mma_kernel(
    const float* __restrict__ Xin, const float* __restrict__ W_edge,
    const float* __restrict__ b_edge, const int* __restrict__ batch) {
    extern __shared__ char smemraw[];
    uint4* sB  = (uint4*)smemraw;                 // [nt32][ks8][lane32] 128 KB
    float* sGu = (float*)(smemraw + 131072);      // 8 KB
    float* sUW = (float*)(smemraw + 139264);      // 8 KB
    int tid = threadIdx.x;

    for (int i = tid; i < 32 * 8 * 32; i += 512) {
        int lane = i & 31, ks = (i >> 5) & 7, nt = i >> 8;
        int gidw = lane >> 2, tigw = lane & 3;
        int n  = nt * 8 + gidw;
        int k0 = ks * 16 + tigw * 2;
        const float* W = (n < D) ? (W_edge + n) : (W_edge + D * D + (n - D));
        float w00 = __ldg(W + k0 * D);
        float w01 = __ldg(W + (k0 + 1) * D);
        float w10 = __ldg(W + (k0 + 8) * D);
        float w11 = __ldg(W + (k0 + 9) * D);
        uint32_t b0h, b0l, b1h, b1l;
        split2(w00, w01, b0h, b0l);
        split2(w10, w11, b1h, b1l);
        sB[i] = make_uint4(b0h, b1h, b0l, b1l);
    }
    for (int i = tid; i < N_GRAPHS * D; i += 512) sGu[i] = g_u[i];
    __syncthreads();
    {
        int j = tid & 127, q4 = tid >> 7;
        float acc[4];
#pragma unroll
        for (int q = 0; q < 4; q++) acc[q] = 0.f;
        const float* W4 = W_edge + 3 * D * D;
        for (int k = 0; k < D; k++) {
            float w = __ldg(W4 + k * D + j);
#pragma unroll
            for (int q = 0; q < 4; q++)
                acc[q] = fmaf(sGu[(q4 * 4 + q) * D + k], w, acc[q]);
        }
        float bj = __ldg(b_edge + j);
#pragma unroll
        for (int q = 0; q < 4; q++) sUW[(q4 * 4 + q) * D + j] = acc[q] + bj;
    }
    __syncthreads();

    int wid = tid >> 5, lane = tid & 31;
    int gid = lane >> 2, tig = lane & 3;
    int wm = wid & 3, wn = wid >> 2;
    bool even = ((tig & 1) == 0);

    for (int tile = blockIdx.x; tile < N_RTILES; tile += gridDim.x) {
        int rbase = tile * 128 + wm * 32;
        float acc[2][8][4];
#pragma unroll
        for (int mt = 0; mt < 2; mt++)
#pragma unroll
            for (int nt = 0; nt < 8; nt++)
#pragma unroll
                for (int q = 0; q < 4; q++) acc[mt][nt][q] = 0.f;

        const float* pA[2];
        const float* pA8[2];
#pragma unroll
        for (int mt = 0; mt < 2; mt++) {
            int r0 = rbase + mt * 16 + gid;
            if (r0 > N_NODES - 1) r0 = N_NODES - 1;
            pA[mt] = Xin + (size_t)r0 * OUTW + tig * 2;
            int r1 = rbase + mt * 16 + 8 + gid;
            if (r1 > N_NODES - 1) r1 = N_NODES - 1;
            pA8[mt] = Xin + (size_t)r1 * OUTW + tig * 2;
        }

#pragma unroll
        for (int ks = 0; ks < 8; ks++) {
            uint32_t ah[2][4], al[2][4];
#pragma unroll
            for (int mt = 0; mt < 2; mt++) {
                float2 v0 = __ldg((const float2*)(pA[mt]  + ks * 16));
                float2 v1 = __ldg((const float2*)(pA8[mt] + ks * 16));
                float2 v2 = __ldg((const float2*)(pA[mt]  + ks * 16 + 8));
                float2 v3 = __ldg((const float2*)(pA8[mt] + ks * 16 + 8));
                split2(v0.x, v0.y, ah[mt][0], al[mt][0]);
                split2(v1.x, v1.y, ah[mt][1], al[mt][1]);
                split2(v2.x, v2.y, ah[mt][2], al[mt][2]);
                split2(v3.x, v3.y, ah[mt][3], al[mt][3]);
            }
#pragma unroll
            for (int nt = 0; nt < 8; nt++) {
                uint4 b = sB[((wn * 8 + nt) * 8 + ks) * 32 + lane];
#pragma unroll
                for (int mt = 0; mt < 2; mt++) {
                    mma_bf16(acc[mt][nt], ah[mt], b.x, b.y);
                    mma_bf16(acc[mt][nt], ah[mt], b.z, b.w);
                    mma_bf16(acc[mt][nt], al[mt], b.x, b.y);
                }
            }
        }

#pragma unroll
        for (int mt = 0; mt < 2; mt++) {
#pragma unroll
            for (int h = 0; h < 2; h++) {
                int row = rbase + mt * 16 + h * 8 + gid;
                bool ok = row < N_NODES;
                int g = __ldg(batch + (ok ? row : N_NODES - 1));
                float* base = g_P12 + (size_t)row * 256;
#pragma unroll
                for (int np = 0; np < 4; np++) {
                    int nt0 = 2 * np, nt1 = 2 * np + 1;
                    float4 v = pair_combine(acc[mt][nt0][h * 2], acc[mt][nt0][h * 2 + 1],
                                            acc[mt][nt1][h * 2], acc[mt][nt1][h * 2 + 1],
                                            even);
                    int n = wn * 64 + (even ? nt0 : nt1) * 8 + (tig & 2) * 2;
                    if (ok) {
                        if (n < D) {
                            float4 uv = *(float4*)(sUW + g * D + n);
                            v.x += uv.x; v.y += uv.y; v.z += uv.z; v.w += uv.w;
                        }
                        *(float4*)(base + n) = v;
                    }
                }
            }
        }
    }
}

// ------------------------- edge kernel: mma.sync ----------------------------
// ea' = relu(ea@We3 + P1'[src] + P2[dst]); red.v4 to agg.
// A-path: LDG.128 + xor-1 exchange; tig-pair float4 epilogue.
__global__ void __launch_bounds__(256, 2) edge_mma_kernel(
    int step0, int store_ea, const float* __restrict__ ext_ea,
    const int* __restrict__ src, const int* __restrict__ dst,
    const float* __restrict__ We3) {
    extern __shared__ uint4 sBe[];   // [nt=16][ks=8][lane=32]
    int tid = threadIdx.x;

    for (int i = tid; i < 16 * 8 * 32; i += 256) {
        int lane = i & 31, ks = (i >> 5) & 7, nt = i >> 8;
        int gidw = lane >> 2, tigw = lane & 3;
        int n  = nt * 8 + gidw;
        int k0 = ks * 16 + tigw * 2;
        float w00 = __ldg(We3 + k0 * D + n);
        float w01 = __ldg(We3 + (k0 + 1) * D + n);
        float w10 = __ldg(We3 + (k0 + 8) * D + n);
        float w11 = __ldg(We3 + (k0 + 9) * D + n);
        uint32_t b0h, b0l, b1h, b1l;
        split2(w00, w01, b0h, b0l);
        split2(w10, w11, b1h, b1l);
        sBe[i] = make_uint4(b0h, b1h, b0l, b1l);
    }
    __syncthreads();

    int wid = tid >> 5, lane = tid & 31;
    int gid = lane >> 2, tig = lane & 3;
    int wm = wid & 3, wn = wid >> 2;
    bool even = ((tig & 1) == 0);
    int colo = ((tig & 1) << 3) + ((tig >> 1) << 2);   // (tig&1)*8 + (tig>>1)*4
    const float* ea_in = step0 ? ext_ea : (const float*)g_ea;

    for (int tile = blockIdx.x; tile < N_TILES; tile += gridDim.x) {
        const float* A = ea_in + (size_t)tile * (128 * 128);
        const float* base0 = A + (wm * 32 + 0 * 16 + gid) * 128 + colo;
        const float* base1 = A + (wm * 32 + 1 * 16 + gid) * 128 + colo;

        int sidx[2][2], didx[2][2];
#pragma unroll
        for (int mt = 0; mt < 2; mt++)
#pragma unroll
            for (int h = 0; h < 2; h++) {
                int r = tile * 128 + wm * 32 + mt * 16 + h * 8 + gid;
                sidx[mt][h] = __ldg(src + r);
                didx[mt][h] = __ldg(dst + r);
            }

        float acc[2][8][4];
#pragma unroll
        for (int mt = 0; mt < 2; mt++)
#pragma unroll
            for (int nt = 0; nt < 8; nt++)
#pragma unroll
                for (int q = 0; q < 4; q++) acc[mt][nt][q] = 0.f;

        float4 cur[2][2], nxt[2][2];
#pragma unroll
        for (int mt = 0; mt < 2; mt++) {
            const float* b = mt ? base1 : base0;
            cur[mt][0] = __ldg((const float4*)b);
            cur[mt][1] = __ldg((const float4*)(b + 8 * 128));
        }
#pragma unroll
        for (int ks = 0; ks < 8; ks++) {
            if (ks < 7) {
#pragma unroll
                for (int mt = 0; mt < 2; mt++) {
                    const float* b = (mt ? base1 : base0) + (ks + 1) * 16;
                    nxt[mt][0] = __ldg((const float4*)b);
                    nxt[mt][1] = __ldg((const float4*)(b + 8 * 128));
                }
            }
            uint32_t ah[2][4], al[2][4];
#pragma unroll
            for (int mt = 0; mt < 2; mt++) {
                frag_from_f4(cur[mt][0], even, ah[mt][0], al[mt][0], ah[mt][2], al[mt][2]);
                frag_from_f4(cur[mt][1], even, ah[mt][1], al[mt][1], ah[mt][3], al[mt][3]);
            }
#pragma unroll
            for (int nt = 0; nt < 8; nt++) {
                uint4 b = sBe[((wn * 8 + nt) * 8 + ks) * 32 + lane];
#pragma unroll
                for (int mt = 0; mt < 2; mt++) {
                    mma_bf16(acc[mt][nt], ah[mt], b.x, b.y);
                    mma_bf16(acc[mt][nt], ah[mt], b.z, b.w);
                    mma_bf16(acc[mt][nt], al[mt], b.x, b.y);
                }
            }
#pragma unroll
            for (int mt = 0; mt < 2; mt++) {
                cur[mt][0] = nxt[mt][0];
                cur[mt][1] = nxt[mt][1];
            }
        }

        // tig-pair float4 epilogue
#pragma unroll
        for (int mt = 0; mt < 2; mt++) {
#pragma unroll
            for (int h = 0; h < 2; h++) {
                int r = tile * 128 + wm * 32 + mt * 16 + h * 8 + gid;
                int s = sidx[mt][h], d = didx[mt][h];
                const float* p1b = g_P12 + (size_t)s * 256;
                const float* p2b = g_P12 + (size_t)d * 256 + 128;
                float* eo = g_ea + (size_t)r * D;
                float* ao = g_agg + (size_t)d * D;
#pragma unroll
                for (int np = 0; np < 4; np++) {
                    int nt0 = 2 * np, nt1 = 2 * np + 1;
                    float4 v = pair_combine(acc[mt][nt0][h * 2], acc[mt][nt0][h * 2 + 1],
                                            acc[mt][nt1][h * 2], acc[mt][nt1][h * 2 + 1],
                                            even);
                    int c = wn * 64 + (even ? nt0 : nt1) * 8 + (tig & 2) * 2;
                    float4 p1 = __ldg((const float4*)(p1b + c));
                    float4 p2 = __ldg((const float4*)(p2b + c));
                    float4 rr;
                    rr.x = fmaxf(v.x + p1.x + p2.x, 0.f);
                    rr.y = fmaxf(v.y + p1.y + p2.y, 0.f);
                    rr.z = fmaxf(v.z + p1.z + p2.z, 0.f);
                    rr.w = fmaxf(v.w + p1.w + p2.w, 0.f);
                    if (store_ea) *(float4*)(eo + c) = rr;
                    red_add4(ao + c, rr);
                }
            }
        }
    }
}

// --------------------------- prep2 (uWn3b only) -----------------------------
__global__ void prep2_kernel(const float* __restrict__ W_node,
                             const float* __restrict__ b_node) {
    int g = blockIdx.x, j = threadIdx.x;
    __shared__ float su[D];
    su[j] = g_u[g * D + j];
    __syncthreads();
    const float* W3 = W_node + 2 * D * D;
    float acc = b_node[j];
#pragma unroll 8
    for (int k = 0; k < D; k++) acc = fmaf(su[k], W3[k * D + j], acc);
    g_uWn3b[g * D + j] = acc;
}

// ------------------------- node kernel (mma.sync, 512 thr) ------------------
__global__ void __launch_bounds__(512, 1) node_mma_kernel(
    const float* __restrict__ Xin, float* __restrict__ Xout,
    const int* __restrict__ batch, const float* __restrict__ W_node) {
    extern __shared__ char smemraw[];
    uint4* sB = (uint4*)smemraw;                  // [nt16][ks16][lane32] 128 KB
    float* sU = (float*)(smemraw + 131072);       // 8 KB
    int tid = threadIdx.x;

    for (int i = tid; i < 16 * 16 * 32; i += 512) {
        int lane = i & 31, ks = (i >> 5) & 15, nt = i >> 9;
        int gidw = lane >> 2, tigw = lane & 3;
        int n  = nt * 8 + gidw;
        int k0 = ks * 16 + tigw * 2;
        float w00 = __ldg(W_node + k0 * D + n);
        float w01 = __ldg(W_node + (k0 + 1) * D + n);
        float w10 = __ldg(W_node + (k0 + 8) * D + n);
        float w11 = __ldg(W_node + (k0 + 9) * D + n);
        uint32_t b0h, b0l, b1h, b1l;
        split2(w00, w01, b0h, b0l);
        split2(w10, w11, b1h, b1l);
        sB[i] = make_uint4(b0h, b1h, b0l, b1l);
    }
    for (int i = tid; i < N_GRAPHS * D; i += 512) sU[i] = g_uWn3b[i];
    __syncthreads();

    int wid = tid >> 5, lane = tid & 31;
    int gid = lane >> 2, tig = lane & 3;
    int wm = wid & 3, wn = wid >> 2;
    bool even = ((tig & 1) == 0);

    for (int tile = blockIdx.x; tile < N_RTILES; tile += gridDim.x) {
        int rbase = tile * 128 + wm * 32;
        int r0c[2], r1c[2];
        float inv0[2], inv1[2];
#pragma unroll
        for (int mt = 0; mt < 2; mt++) {
            int r0 = rbase + mt * 16 + gid;      if (r0 > N_NODES - 1) r0 = N_NODES - 1;
            int r1 = rbase + mt * 16 + 8 + gid;  if (r1 > N_NODES - 1) r1 = N_NODES - 1;
            r0c[mt] = r0; r1c[mt] = r1;
            inv0[mt] = __ldg(&g_invN[r0]);
            inv1[mt] = __ldg(&g_invN[r1]);
        }

        float acc[2][4][4];
#pragma unroll
        for (int mt = 0; mt < 2; mt++)
#pragma unroll
            for (int nt = 0; nt < 4; nt++)
#pragma unroll
                for (int q = 0; q < 4; q++) acc[mt][nt][q] = 0.f;

#pragma unroll
        for (int ks = 0; ks < 16; ks++) {
            uint32_t ah[2][4], al[2][4];
#pragma unroll
            for (int mt = 0; mt < 2; mt++) {
                float2 v0, v1, v2, v3;
                if (ks < 8) {
                    const float* p0 = Xin + (size_t)r0c[mt] * OUTW + ks * 16 + tig * 2;
                    const float* p1 = Xin + (size_t)r1c[mt] * OUTW + ks * 16 + tig * 2;
                    v0 = __ldg((const float2*)p0);
                    v1 = __ldg((const float2*)p1);
                    v2 = __ldg((const float2*)(p0 + 8));
                    v3 = __ldg((const float2*)(p1 + 8));
                } else {
                    const float* p0 = g_agg + (size_t)r0c[mt] * D + (ks - 8) * 16 + tig * 2;
                    const float* p1 = g_agg + (size_t)r1c[mt] * D + (ks - 8) * 16 + tig * 2;
                    v0 = __ldg((const float2*)p0);
                    v1 = __ldg((const float2*)p1);
                    v2 = __ldg((const float2*)(p0 + 8));
                    v3 = __ldg((const float2*)(p1 + 8));
                    v0.x *= inv0[mt]; v0.y *= inv0[mt];
                    v1.x *= inv1[mt]; v1.y *= inv1[mt];
                    v2.x *= inv0[mt]; v2.y *= inv0[mt];
                    v3.x *= inv1[mt]; v3.y *= inv1[mt];
                }
                split2(v0.x, v0.y, ah[mt][0], al[mt][0]);
                split2(v1.x, v1.y, ah[mt][1], al[mt][1]);
                split2(v2.x, v2.y, ah[mt][2], al[mt][2]);
                split2(v3.x, v3.y, ah[mt][3], al[mt][3]);
            }
#pragma unroll
            for (int nt = 0; nt < 4; nt++) {
                uint4 b = sB[((wn * 4 + nt) * 16 + ks) * 32 + lane];
#pragma unroll
                for (int mt = 0; mt < 2; mt++) {
                    mma_bf16(acc[mt][nt], ah[mt], b.x, b.y);
                    mma_bf16(acc[mt][nt], ah[mt], b.z, b.w);
                    mma_bf16(acc[mt][nt], al[mt], b.x, b.y);
                }
            }
        }

        // all agg reads of this tile done before epilogue zeroes agg rows
        __syncthreads();

        // tig-pair float4 epilogue: Xout rows + red.v4 + agg zeroing
#pragma unroll
        for (int mt = 0; mt < 2; mt++) {
#pragma unroll
            for (int h = 0; h < 2; h++) {
                int row = rbase + mt * 16 + h * 8 + gid;
                bool ok = row < N_NODES;
                int g = __ldg(batch + (ok ? row : N_NODES - 1));
                float* xo = Xout + (size_t)row * OUTW;
                float* ag = g_agg + (size_t)row * D;
#pragma unroll
                for (int np = 0; np < 2; np++) {
                    int nt0 = 2 * np, nt1 = 2 * np + 1;
                    float4 v = pair_combine(acc[mt][nt0][h * 2], acc[mt][nt0][h * 2 + 1],
                                            acc[mt][nt1][h * 2], acc[mt][nt1][h * 2 + 1],
                                            even);
                    int c = wn * 32 + (even ? nt0 : nt1) * 8 + (tig & 2) * 2;
                    if (ok) {
                        float4 uv = *(float4*)(sU + g * D + c);
                        float4 rr;
                        rr.x = fmaxf(v.x + uv.x, 0.f);
                        rr.y = fmaxf(v.y + uv.y, 0.f);
                        rr.z = fmaxf(v.z + uv.z, 0.f);
                        rr.w = fmaxf(v.w + uv.w, 0.f);
                        *(float4*)(xo + c) = rr;
                        red_add4(g_gsum + g * D + c, rr);
                        *(float4*)(ag + c) = make_float4(0.f, 0.f, 0.f, 0.f);
                    }
                }
            }
        }
    }
}

// ------------------------------ global kernel ------------------------------
__global__ void global_kernel(const float* __restrict__ W_glob,
                              const float* __restrict__ b_glob,
                              float* __restrict__ out_g) {
    int g = blockIdx.x;
    int j = threadIdx.x;
    __shared__ float su[D], sm[D];
    su[j] = g_u[g * D + j];
    sm[j] = g_gsum[g * D + j] * g_invG[g];
    g_gsum[g * D + j] = 0.f;
    __syncthreads();
    float acc = b_glob[j];
#pragma unroll 4
    for (int k = 0; k < D; k++) acc = fmaf(su[k], W_glob[k * D + j], acc);
#pragma unroll 4
    for (int k = 0; k < D; k++) acc = fmaf(sm[k], W_glob[(D + k) * D + j], acc);
    float r = fmaxf(acc, 0.f);
    out_g[(size_t)g * OUTW + j] = r;
    g_u[g * D + j] = r;
}

// --------------------------------- launch ----------------------------------
extern "C" void kernel_launch(void* const* d_in, const int* in_sizes, int n_in,
                              void* d_out, int out_size) {
    const float* x      = (const float*)d_in[0];
    const int*   ei     = (const int*)d_in[1];
    const float* ea     = (const float*)d_in[2];
    const float* u      = (const float*)d_in[3];
    const int*   batch  = (const int*)d_in[4];
    const float* W_edge = (const float*)d_in[5];
    const float* b_edge = (const float*)d_in[6];
    const float* W_node = (const float*)d_in[7];
    const float* b_node = (const float*)d_in[8];
    const float* W_glob = (const float*)d_in[9];
    const float* b_glob = (const float*)d_in[10];

    const int* src = ei;
    const int* dstp = ei + N_EDGES;

    float* out   = (float*)d_out;
    float* out_x = out;                            // 50000 x 512
    float* out_g = out + (size_t)N_NODES * OUTW;   // 16 x 512

    const int MV_SMEM   = 131072 + 8192 + 8192;    // 147456
    const int EDGE_SMEM = 16 * 8 * 32 * 16;        // 64 KB
    const int NODE_SMEM = 131072 + 8192;           // 139264

    cudaFuncSetAttribute(matvec_mma_kernel, cudaFuncAttributeMaxDynamicSharedMemorySize, MV_SMEM);
    cudaFuncSetAttribute(edge_mma_kernel,   cudaFuncAttributeMaxDynamicSharedMemorySize, EDGE_SMEM);
    cudaFuncSetAttribute(node_mma_kernel,   cudaFuncAttributeMaxDynamicSharedMemorySize, NODE_SMEM);

    // launch order: index 3 (ncu capture point) = edge_mma_kernel
    init_kernel<<<2048, 256>>>(x, u, out_x, out_g);                          // 0
    matvec_mma_kernel<<<148, 512, MV_SMEM>>>(out_x, W_edge, b_edge, batch);  // 1 (t=0)
    hist_kernel<<<1024, 256>>>(dstp, batch);                                 // 2
    edge_mma_kernel<<<296, 256, EDGE_SMEM>>>(1, 1, ea, src, dstp,            // 3 PROFILED
                                             W_edge + 2 * D * D);
    finalize_counts_kernel<<<256, 256>>>();                                  // 4

    for (int t = 0; t < 3; t++) {
        const float* Xt = out_x + t * D;
        float*       Xn = out_x + (t + 1) * D;

        prep2_kernel<<<16, 128>>>(W_node, b_node);
        node_mma_kernel<<<148, 512, NODE_SMEM>>>(Xt, Xn, batch, W_node);
        global_kernel<<<16, 128>>>(W_glob, b_glob, out_g + (t + 1) * D);

        if (t < 2) {
            matvec_mma_kernel<<<148, 512, MV_SMEM>>>(Xn, W_edge, b_edge, batch);
            edge_mma_kernel<<<296, 256, EDGE_SMEM>>>(0, (t + 1) < 2 ? 1 : 0, ea,
                                                     src, dstp, W_edge + 2 * D * D);
        }
    }
}

// round 16
// speedup vs baseline: 1.0962x; 1.0594x over previous
#include <cuda_runtime.h>
#include <cstdint>

// ---------------------------------------------------------------------------
// MetaMLP (3-step GraphNet) on GB300 — R12/R15 config (measured best) + PDL:
// mma.sync everywhere; tig-pair float4 epilogues; LDG.128+xor-1 edge A-path;
// programmatic dependent launch overlaps W-prepack with predecessor tails.
// ---------------------------------------------------------------------------

#define D 128
static constexpr int N_NODES  = 50000;
static constexpr int N_EDGES  = 800000;
static constexpr int N_GRAPHS = 16;
static constexpr int OUTW     = 4 * D;          // 512 output cols per row
static constexpr int N_TILES  = N_EDGES / 128;  // 6250
static constexpr int N_RTILES = (N_NODES + 127) / 128;  // 391

typedef unsigned long long u64;

// ------------------------- device scratch (no allocs) ----------------------
__device__ float g_ea  [(size_t)N_EDGES  * D];
__device__ float g_P12 [(size_t)N_NODES  * 2 * D];   // [P1+uW4b+b | P2]
__device__ float g_agg [(size_t)N_NODES  * D];
__device__ float g_u    [N_GRAPHS * D];
__device__ float g_uWn3b[N_GRAPHS * D];
__device__ float g_gsum [N_GRAPHS * D];
__device__ float g_invN [N_NODES];
__device__ float g_invG [N_GRAPHS];

// ------------------------------ helpers ------------------------------------
__device__ __forceinline__ void gdc_launch_dependents() {
    asm volatile("griddepcontrol.launch_dependents;" ::: "memory");
}
__device__ __forceinline__ void gdc_wait() {
    asm volatile("griddepcontrol.wait;" ::: "memory");
}
__device__ __forceinline__ uint32_t cvt_bf16x2(float a, float b) {
    uint32_t r;
    asm("cvt.rn.bf16x2.f32 %0, %1, %2;" : "=r"(r) : "f"(b), "f"(a));
    return r;
}
__device__ __forceinline__ void split2(float x, float y, uint32_t& hi, uint32_t& lo) {
    hi = cvt_bf16x2(x, y);
    float hx = __uint_as_float(hi << 16);
    float hy = __uint_as_float(hi & 0xffff0000u);
    lo = cvt_bf16x2(x - hx, y - hy);
}
__device__ __forceinline__ void mma_bf16(float* d, const uint32_t* a, uint32_t b0, uint32_t b1) {
    asm volatile("mma.sync.aligned.m16n8k16.row.col.f32.bf16.bf16.f32 "
        "{%0,%1,%2,%3}, {%4,%5,%6,%7}, {%8,%9}, {%0,%1,%2,%3};"
        : "+f"(d[0]), "+f"(d[1]), "+f"(d[2]), "+f"(d[3])
        : "r"(a[0]), "r"(a[1]), "r"(a[2]), "r"(a[3]), "r"(b0), "r"(b1));
}
__device__ __forceinline__ void red_add4(float* addr, float4 v) {
    asm volatile("red.global.add.v4.f32 [%0], {%1, %2, %3, %4};"
                 :: "l"(addr), "f"(v.x), "f"(v.y), "f"(v.z), "f"(v.w) : "memory");
}

// tig-pair combine: even tig returns nt0's float4, odd tig returns nt1's.
__device__ __forceinline__ float4 pair_combine(float a0, float a1, float b0, float b1,
                                               bool even) {
    float sa0 = __shfl_xor_sync(0xffffffffu, a0, 1);
    float sa1 = __shfl_xor_sync(0xffffffffu, a1, 1);
    float sb0 = __shfl_xor_sync(0xffffffffu, b0, 1);
    float sb1 = __shfl_xor_sync(0xffffffffu, b1, 1);
    return even ? make_float4(a0, a1, sa0, sa1) : make_float4(sb0, sb1, b0, b1);
}

// widened A-fragment build: lane loaded float4 at col (tig&1)*8+(tig>>1)*4.
__device__ __forceinline__ void frag_from_f4(float4 f, bool even,
                                             uint32_t& rlo_h, uint32_t& rlo_l,
                                             uint32_t& rhi_h, uint32_t& rhi_l) {
    uint32_t h01, l01, h23, l23;
    split2(f.x, f.y, h01, l01);
    split2(f.z, f.w, h23, l23);
    uint32_t sh01 = __shfl_xor_sync(0xffffffffu, h01, 1);
    uint32_t sl01 = __shfl_xor_sync(0xffffffffu, l01, 1);
    uint32_t sh23 = __shfl_xor_sync(0xffffffffu, h23, 1);
    uint32_t sl23 = __shfl_xor_sync(0xffffffffu, l23, 1);
    rlo_h = even ? h01 : sh23;
    rlo_l = even ? l01 : sl23;
    rhi_h = even ? sh01 : h23;
    rhi_l = even ? sl01 : l23;
}

// ------------------------------ init (launch 0) -----------------------------
__global__ void init_kernel(const float* __restrict__ x, const float* __restrict__ u,
                            float* __restrict__ out_x, float* __restrict__ out_g) {
    gdc_launch_dependents();
    int stride = gridDim.x * blockDim.x;
    int tid0 = blockIdx.x * blockDim.x + threadIdx.x;
    const int NQ = N_NODES * D / 4;
    for (int i = tid0; i < NQ; i += stride) {
        int r = i >> 5, c = i & 31;
        float4 v = __ldg((const float4*)x + i);
        *((float4*)(out_x + (size_t)r * OUTW) + c) = v;
        ((float4*)g_agg)[i] = make_float4(0.f, 0.f, 0.f, 0.f);
    }
    for (int i = tid0; i < N_GRAPHS * D; i += stride) {
        int r = i >> 7, c = i & (D - 1);
        out_g[(size_t)r * OUTW + c] = u[i];
        g_u[i] = u[i];
    }
    for (int i = tid0; i < N_NODES; i += stride) g_invN[i] = 0.f;
    for (int i = tid0; i < N_GRAPHS; i += stride) g_invG[i] = 0.f;
}

// ------------------------------ hist / finalize ------------------------------
__global__ void hist_kernel(const int* __restrict__ dst, const int* __restrict__ batch) {
    gdc_launch_dependents();
    int stride = gridDim.x * blockDim.x;
    int tid0 = blockIdx.x * blockDim.x + threadIdx.x;
    for (int i = tid0; i < N_EDGES; i += stride) atomicAdd(&g_invN[dst[i]], 1.f);
    for (int i = tid0; i < N_NODES; i += stride) atomicAdd(&g_invG[batch[i]], 1.f);
}

__global__ void finalize_counts_kernel() {
    gdc_launch_dependents();
    int stride = gridDim.x * blockDim.x;
    int tid0 = blockIdx.x * blockDim.x + threadIdx.x;
    for (int i = tid0; i < N_NODES; i += stride) g_invN[i] = 1.f / fmaxf(g_invN[i], 1.f);
    for (int i = tid0; i < N_GRAPHS; i += stride) g_invG[i] = 1.f / fmaxf(g_invG[i], 1.f);
}

// ----------------------- matvec P1/P2 (mma.sync, 512 thr, PSS) ---------------
__global__ void __launch_bounds__(512, 1) matvec_mma_kernel(
    const float* __restrict__ Xin, const float* __restrict__ W_edge,
    const float* __restrict__ b_edge, const int* __restrict__ batch) {
    extern __shared__ char smemraw[];
    uint4* sB  = (uint4*)smemraw;                 // [nt32][ks8][lane32] 128 KB
    float* sGu = (float*)(smemraw + 131072);      // 8 KB
    float* sUW = (float*)(smemraw + 139264);      // 8 KB
    int tid = threadIdx.x;
    gdc_launch_dependents();

    // independent prologue: W prepack (const inputs only)
    for (int i = tid; i < 32 * 8 * 32; i += 512) {
        int lane = i & 31, ks = (i >> 5) & 7, nt = i >> 8;
        int gidw = lane >> 2, tigw = lane & 3;
        int n  = nt * 8 + gidw;
        int k0 = ks * 16 + tigw * 2;
        const float* W = (n < D) ? (W_edge + n) : (W_edge + D * D + (n - D));
        float w00 = __ldg(W + k0 * D);
        float w01 = __ldg(W + (k0 + 1) * D);
        float w10 = __ldg(W + (k0 + 8) * D);
        float w11 = __ldg(W + (k0 + 9) * D);
        uint32_t b0h, b0l, b1h, b1l;
        split2(w00, w01, b0h, b0l);
        split2(w10, w11, b1h, b1l);
        sB[i] = make_uint4(b0h, b1h, b0l, b1l);
    }
    gdc_wait();   // predecessor (global / init) complete: g_u, Xin valid

    for (int i = tid; i < N_GRAPHS * D; i += 512) sGu[i] = g_u[i];
    __syncthreads();
    {
        int j = tid & 127, q4 = tid >> 7;
        float acc[4];
#pragma unroll
        for (int q = 0; q < 4; q++) acc[q] = 0.f;
        const float* W4 = W_edge + 3 * D * D;
        for (int k = 0; k < D; k++) {
            float w = __ldg(W4 + k * D + j);
#pragma unroll
            for (int q = 0; q < 4; q++)
                acc[q] = fmaf(sGu[(q4 * 4 + q) * D + k], w, acc[q]);
        }
        float bj = __ldg(b_edge + j);
#pragma unroll
        for (int q = 0; q < 4; q++) sUW[(q4 * 4 + q) * D + j] = acc[q] + bj;
    }
    __syncthreads();

    int wid = tid >> 5, lane = tid & 31;
    int gid = lane >> 2, tig = lane & 3;
    int wm = wid & 3, wn = wid >> 2;
    bool even = ((tig & 1) == 0);

    for (int tile = blockIdx.x; tile < N_RTILES; tile += gridDim.x) {
        int rbase = tile * 128 + wm * 32;
        float acc[2][8][4];
#pragma unroll
        for (int mt = 0; mt < 2; mt++)
#pragma unroll
            for (int nt = 0; nt < 8; nt++)
#pragma unroll
                for (int q = 0; q < 4; q++) acc[mt][nt][q] = 0.f;

        const float* pA[2];
        const float* pA8[2];
#pragma unroll
        for (int mt = 0; mt < 2; mt++) {
            int r0 = rbase + mt * 16 + gid;
            if (r0 > N_NODES - 1) r0 = N_NODES - 1;
            pA[mt] = Xin + (size_t)r0 * OUTW + tig * 2;
            int r1 = rbase + mt * 16 + 8 + gid;
            if (r1 > N_NODES - 1) r1 = N_NODES - 1;
            pA8[mt] = Xin + (size_t)r1 * OUTW + tig * 2;
        }

#pragma unroll
        for (int ks = 0; ks < 8; ks++) {
            uint32_t ah[2][4], al[2][4];
#pragma unroll
            for (int mt = 0; mt < 2; mt++) {
                float2 v0 = __ldg((const float2*)(pA[mt]  + ks * 16));
                float2 v1 = __ldg((const float2*)(pA8[mt] + ks * 16));
                float2 v2 = __ldg((const float2*)(pA[mt]  + ks * 16 + 8));
                float2 v3 = __ldg((const float2*)(pA8[mt] + ks * 16 + 8));
                split2(v0.x, v0.y, ah[mt][0], al[mt][0]);
                split2(v1.x, v1.y, ah[mt][1], al[mt][1]);
                split2(v2.x, v2.y, ah[mt][2], al[mt][2]);
                split2(v3.x, v3.y, ah[mt][3], al[mt][3]);
            }
#pragma unroll
            for (int nt = 0; nt < 8; nt++) {
                uint4 b = sB[((wn * 8 + nt) * 8 + ks) * 32 + lane];
#pragma unroll
                for (int mt = 0; mt < 2; mt++) {
                    mma_bf16(acc[mt][nt], ah[mt], b.x, b.y);
                    mma_bf16(acc[mt][nt], ah[mt], b.z, b.w);
                    mma_bf16(acc[mt][nt], al[mt], b.x, b.y);
                }
            }
        }

#pragma unroll
        for (int mt = 0; mt < 2; mt++) {
#pragma unroll
            for (int h = 0; h < 2; h++) {
                int row = rbase + mt * 16 + h * 8 + gid;
                bool ok = row < N_NODES;
                int g = __ldg(batch + (ok ? row : N_NODES - 1));
                float* base = g_P12 + (size_t)row * 256;
#pragma unroll
                for (int np = 0; np < 4; np++) {
                    int nt0 = 2 * np, nt1 = 2 * np + 1;
                    float4 v = pair_combine(acc[mt][nt0][h * 2], acc[mt][nt0][h * 2 + 1],
                                            acc[mt][nt1][h * 2], acc[mt][nt1][h * 2 + 1],
                                            even);
                    int n = wn * 64 + (even ? nt0 : nt1) * 8 + (tig & 2) * 2;
                    if (ok) {
                        if (n < D) {
                            float4 uv = *(float4*)(sUW + g * D + n);
                            v.x += uv.x; v.y += uv.y; v.z += uv.z; v.w += uv.w;
                        }
                        *(float4*)(base + n) = v;
                    }
                }
            }
        }
    }
}

// ------------------------- edge kernel: mma.sync (PSS) -----------------------
__global__ void __launch_bounds__(256, 2) edge_mma_kernel(
    int step0, int store_ea, const float* __restrict__ ext_ea,
    const int* __restrict__ src, const int* __restrict__ dst,
    const float* __restrict__ We3) {
    extern __shared__ uint4 sBe[];   // [nt=16][ks=8][lane=32]
    int tid = threadIdx.x;
    gdc_launch_dependents();

    // independent prologue: W prepack (const input only)
    for (int i = tid; i < 16 * 8 * 32; i += 256) {
        int lane = i & 31, ks = (i >> 5) & 7, nt = i >> 8;
        int gidw = lane >> 2, tigw = lane & 3;
        int n  = nt * 8 + gidw;
        int k0 = ks * 16 + tigw * 2;
        float w00 = __ldg(We3 + k0 * D + n);
        float w01 = __ldg(We3 + (k0 + 1) * D + n);
        float w10 = __ldg(We3 + (k0 + 8) * D + n);
        float w11 = __ldg(We3 + (k0 + 9) * D + n);
        uint32_t b0h, b0l, b1h, b1l;
        split2(w00, w01, b0h, b0l);
        split2(w10, w11, b1h, b1l);
        sBe[i] = make_uint4(b0h, b1h, b0l, b1l);
    }
    gdc_wait();   // predecessor (matvec) complete: g_P12 valid
    __syncthreads();

    int wid = tid >> 5, lane = tid & 31;
    int gid = lane >> 2, tig = lane & 3;
    int wm = wid & 3, wn = wid >> 2;
    bool even = ((tig & 1) == 0);
    int colo = ((tig & 1) << 3) + ((tig >> 1) << 2);
    const float* ea_in = step0 ? ext_ea : (const float*)g_ea;

    for (int tile = blockIdx.x; tile < N_TILES; tile += gridDim.x) {
        const float* A = ea_in + (size_t)tile * (128 * 128);
        const float* base0 = A + (wm * 32 + 0 * 16 + gid) * 128 + colo;
        const float* base1 = A + (wm * 32 + 1 * 16 + gid) * 128 + colo;

        int sidx[2][2], didx[2][2];
#pragma unroll
        for (int mt = 0; mt < 2; mt++)
#pragma unroll
            for (int h = 0; h < 2; h++) {
                int r = tile * 128 + wm * 32 + mt * 16 + h * 8 + gid;
                sidx[mt][h] = __ldg(src + r);
                didx[mt][h] = __ldg(dst + r);
            }

        float acc[2][8][4];
#pragma unroll
        for (int mt = 0; mt < 2; mt++)
#pragma unroll
            for (int nt = 0; nt < 8; nt++)
#pragma unroll
                for (int q = 0; q < 4; q++) acc[mt][nt][q] = 0.f;

        float4 cur[2][2], nxt[2][2];
#pragma unroll
        for (int mt = 0; mt < 2; mt++) {
            const float* b = mt ? base1 : base0;
            cur[mt][0] = __ldg((const float4*)b);
            cur[mt][1] = __ldg((const float4*)(b + 8 * 128));
        }
#pragma unroll
        for (int ks = 0; ks < 8; ks++) {
            if (ks < 7) {
#pragma unroll
                for (int mt = 0; mt < 2; mt++) {
                    const float* b = (mt ? base1 : base0) + (ks + 1) * 16;
                    nxt[mt][0] = __ldg((const float4*)b);
                    nxt[mt][1] = __ldg((const float4*)(b + 8 * 128));
                }
            }
            uint32_t ah[2][4], al[2][4];
#pragma unroll
            for (int mt = 0; mt < 2; mt++) {
                frag_from_f4(cur[mt][0], even, ah[mt][0], al[mt][0], ah[mt][2], al[mt][2]);
                frag_from_f4(cur[mt][1], even, ah[mt][1], al[mt][1], ah[mt][3], al[mt][3]);
            }
#pragma unroll
            for (int nt = 0; nt < 8; nt++) {
                uint4 b = sBe[((wn * 8 + nt) * 8 + ks) * 32 + lane];
#pragma unroll
                for (int mt = 0; mt < 2; mt++) {
                    mma_bf16(acc[mt][nt], ah[mt], b.x, b.y);
                    mma_bf16(acc[mt][nt], ah[mt], b.z, b.w);
                    mma_bf16(acc[mt][nt], al[mt], b.x, b.y);
                }
            }
#pragma unroll
            for (int mt = 0; mt < 2; mt++) {
                cur[mt][0] = nxt[mt][0];
                cur[mt][1] = nxt[mt][1];
            }
        }

#pragma unroll
        for (int mt = 0; mt < 2; mt++) {
#pragma unroll
            for (int h = 0; h < 2; h++) {
                int r = tile * 128 + wm * 32 + mt * 16 + h * 8 + gid;
                int s = sidx[mt][h], d = didx[mt][h];
                const float* p1b = g_P12 + (size_t)s * 256;
                const float* p2b = g_P12 + (size_t)d * 256 + 128;
                float* eo = g_ea + (size_t)r * D;
                float* ao = g_agg + (size_t)d * D;
#pragma unroll
                for (int np = 0; np < 4; np++) {
                    int nt0 = 2 * np, nt1 = 2 * np + 1;
                    float4 v = pair_combine(acc[mt][nt0][h * 2], acc[mt][nt0][h * 2 + 1],
                                            acc[mt][nt1][h * 2], acc[mt][nt1][h * 2 + 1],
                                            even);
                    int c = wn * 64 + (even ? nt0 : nt1) * 8 + (tig & 2) * 2;
                    float4 p1 = __ldg((const float4*)(p1b + c));
                    float4 p2 = __ldg((const float4*)(p2b + c));
                    float4 rr;
                    rr.x = fmaxf(v.x + p1.x + p2.x, 0.f);
                    rr.y = fmaxf(v.y + p1.y + p2.y, 0.f);
                    rr.z = fmaxf(v.z + p1.z + p2.z, 0.f);
                    rr.w = fmaxf(v.w + p1.w + p2.w, 0.f);
                    if (store_ea) *(float4*)(eo + c) = rr;
                    red_add4(ao + c, rr);
                }
            }
        }
    }
}

// --------------------------- prep2 (uWn3b only) -----------------------------
__global__ void prep2_kernel(const float* __restrict__ W_node,
                             const float* __restrict__ b_node) {
    gdc_launch_dependents();
    int g = blockIdx.x, j = threadIdx.x;
    __shared__ float su[D];
    su[j] = g_u[g * D + j];
    __syncthreads();
    const float* W3 = W_node + 2 * D * D;
    float acc = b_node[j];
#pragma unroll 8
    for (int k = 0; k < D; k++) acc = fmaf(su[k], W3[k * D + j], acc);
    g_uWn3b[g * D + j] = acc;
}

// ------------------------- node kernel (mma.sync, PSS) -----------------------
__global__ void __launch_bounds__(512, 1) node_mma_kernel(
    const float* __restrict__ Xin, float* __restrict__ Xout,
    const int* __restrict__ batch, const float* __restrict__ W_node) {
    extern __shared__ char smemraw[];
    uint4* sB = (uint4*)smemraw;                  // [nt16][ks16][lane32] 128 KB
    float* sU = (float*)(smemraw + 131072);       // 8 KB
    int tid = threadIdx.x;
    gdc_launch_dependents();

    // independent prologue: W prepack (const input only)
    for (int i = tid; i < 16 * 16 * 32; i += 512) {
        int lane = i & 31, ks = (i >> 5) & 15, nt = i >> 9;
        int gidw = lane >> 2, tigw = lane & 3;
        int n  = nt * 8 + gidw;
        int k0 = ks * 16 + tigw * 2;
        float w00 = __ldg(W_node + k0 * D + n);
        float w01 = __ldg(W_node + (k0 + 1) * D + n);
        float w10 = __ldg(W_node + (k0 + 8) * D + n);
        float w11 = __ldg(W_node + (k0 + 9) * D + n);
        uint32_t b0h, b0l, b1h, b1l;
        split2(w00, w01, b0h, b0l);
        split2(w10, w11, b1h, b1l);
        sB[i] = make_uint4(b0h, b1h, b0l, b1l);
    }
    gdc_wait();   // predecessor (prep2) complete: g_uWn3b, g_agg valid

    for (int i = tid; i < N_GRAPHS * D; i += 512) sU[i] = g_uWn3b[i];
    __syncthreads();

    int wid = tid >> 5, lane = tid & 31;
    int gid = lane >> 2, tig = lane & 3;
    int wm = wid & 3, wn = wid >> 2;
    bool even = ((tig & 1) == 0);

    for (int tile = blockIdx.x; tile < N_RTILES; tile += gridDim.x) {
        int rbase = tile * 128 + wm * 32;
        int r0c[2], r1c[2];
        float inv0[2], inv1[2];
#pragma unroll
        for (int mt = 0; mt < 2; mt++) {
            int r0 = rbase + mt * 16 + gid;      if (r0 > N_NODES - 1) r0 = N_NODES - 1;
            int r1 = rbase + mt * 16 + 8 + gid;  if (r1 > N_NODES - 1) r1 = N_NODES - 1;
            r0c[mt] = r0; r1c[mt] = r1;
            inv0[mt] = __ldg(&g_invN[r0]);
            inv1[mt] = __ldg(&g_invN[r1]);
        }

        float acc[2][4][4];
#pragma unroll
        for (int mt = 0; mt < 2; mt++)
#pragma unroll
            for (int nt = 0; nt < 4; nt++)
#pragma unroll
                for (int q = 0; q < 4; q++) acc[mt][nt][q] = 0.f;

#pragma unroll
        for (int ks = 0; ks < 16; ks++) {
            uint32_t ah[2][4], al[2][4];
#pragma unroll
            for (int mt = 0; mt < 2; mt++) {
                float2 v0, v1, v2, v3;
                if (ks < 8) {
                    const float* p0 = Xin + (size_t)r0c[mt] * OUTW + ks * 16 + tig * 2;
                    const float* p1 = Xin + (size_t)r1c[mt] * OUTW + ks * 16 + tig * 2;
                    v0 = __ldg((const float2*)p0);
                    v1 = __ldg((const float2*)p1);
                    v2 = __ldg((const float2*)(p0 + 8));
                    v3 = __ldg((const float2*)(p1 + 8));
                } else {
                    const float* p0 = g_agg + (size_t)r0c[mt] * D + (ks - 8) * 16 + tig * 2;
                    const float* p1 = g_agg + (size_t)r1c[mt] * D + (ks - 8) * 16 + tig * 2;
                    v0 = __ldg((const float2*)p0);
                    v1 = __ldg((const float2*)p1);
                    v2 = __ldg((const float2*)(p0 + 8));
                    v3 = __ldg((const float2*)(p1 + 8));
                    v0.x *= inv0[mt]; v0.y *= inv0[mt];
                    v1.x *= inv1[mt]; v1.y *= inv1[mt];
                    v2.x *= inv0[mt]; v2.y *= inv0[mt];
                    v3.x *= inv1[mt]; v3.y *= inv1[mt];
                }
                split2(v0.x, v0.y, ah[mt][0], al[mt][0]);
                split2(v1.x, v1.y, ah[mt][1], al[mt][1]);
                split2(v2.x, v2.y, ah[mt][2], al[mt][2]);
                split2(v3.x, v3.y, ah[mt][3], al[mt][3]);
            }
#pragma unroll
            for (int nt = 0; nt < 4; nt++) {
                uint4 b = sB[((wn * 4 + nt) * 16 + ks) * 32 + lane];
#pragma unroll
                for (int mt = 0; mt < 2; mt++) {
                    mma_bf16(acc[mt][nt], ah[mt], b.x, b.y);
                    mma_bf16(acc[mt][nt], ah[mt], b.z, b.w);
                    mma_bf16(acc[mt][nt], al[mt], b.x, b.y);
                }
            }
        }

        // all agg reads of this tile done before epilogue zeroes agg rows
        __syncthreads();

        // tig-pair float4 epilogue: Xout rows + red.v4 + agg zeroing
#pragma unroll
        for (int mt = 0; mt < 2; mt++) {
#pragma unroll
            for (int h = 0; h < 2; h++) {
                int row = rbase + mt * 16 + h * 8 + gid;
                bool ok = row < N_NODES;
                int g = __ldg(batch + (ok ? row : N_NODES - 1));
                float* xo = Xout + (size_t)row * OUTW;
                float* ag = g_agg + (size_t)row * D;
#pragma unroll
                for (int np = 0; np < 2; np++) {
                    int nt0 = 2 * np, nt1 = 2 * np + 1;
                    float4 v = pair_combine(acc[mt][nt0][h * 2], acc[mt][nt0][h * 2 + 1],
                                            acc[mt][nt1][h * 2], acc[mt][nt1][h * 2 + 1],
                                            even);
                    int c = wn * 32 + (even ? nt0 : nt1) * 8 + (tig & 2) * 2;
                    if (ok) {
                        float4 uv = *(float4*)(sU + g * D + c);
                        float4 rr;
                        rr.x = fmaxf(v.x + uv.x, 0.f);
                        rr.y = fmaxf(v.y + uv.y, 0.f);
                        rr.z = fmaxf(v.z + uv.z, 0.f);
                        rr.w = fmaxf(v.w + uv.w, 0.f);
                        *(float4*)(xo + c) = rr;
                        red_add4(g_gsum + g * D + c, rr);
                        *(float4*)(ag + c) = make_float4(0.f, 0.f, 0.f, 0.f);
                    }
                }
            }
        }
    }
}

// ------------------------------ global kernel ------------------------------
__global__ void global_kernel(const float* __restrict__ W_glob,
                              const float* __restrict__ b_glob,
                              float* __restrict__ out_g) {
    gdc_launch_dependents();
    int g = blockIdx.x;
    int j = threadIdx.x;
    __shared__ float su[D], sm[D];
    su[j] = g_u[g * D + j];
    sm[j] = g_gsum[g * D + j] * g_invG[g];
    g_gsum[g * D + j] = 0.f;
    __syncthreads();
    float acc = b_glob[j];
#pragma unroll 4
    for (int k = 0; k < D; k++) acc = fmaf(su[k], W_glob[k * D + j], acc);
#pragma unroll 4
    for (int k = 0; k < D; k++) acc = fmaf(sm[k], W_glob[(D + k) * D + j], acc);
    float r = fmaxf(acc, 0.f);
    out_g[(size_t)g * OUTW + j] = r;
    g_u[g * D + j] = r;
}

// ----------------------------- PSS launch helper ----------------------------
template <typename F, typename... Args>
static void launch_pss(F* k, dim3 grid, dim3 block, size_t smem, Args... args) {
    cudaLaunchConfig_t cfg = {};
    cfg.gridDim = grid;
    cfg.blockDim = block;
    cfg.dynamicSmemBytes = smem;
    cfg.stream = 0;
    cudaLaunchAttribute attr[1];
    attr[0].id = cudaLaunchAttributeProgrammaticStreamSerialization;
    attr[0].val.programmaticStreamSerializationAllowed = 1;
    cfg.attrs = attr;
    cfg.numAttrs = 1;
    cudaLaunchKernelEx(&cfg, k, args...);
}

// --------------------------------- launch ----------------------------------
extern "C" void kernel_launch(void* const* d_in, const int* in_sizes, int n_in,
                              void* d_out, int out_size) {
    const float* x      = (const float*)d_in[0];
    const int*   ei     = (const int*)d_in[1];
    const float* ea     = (const float*)d_in[2];
    const float* u      = (const float*)d_in[3];
    const int*   batch  = (const int*)d_in[4];
    const float* W_edge = (const float*)d_in[5];
    const float* b_edge = (const float*)d_in[6];
    const float* W_node = (const float*)d_in[7];
    const float* b_node = (const float*)d_in[8];
    const float* W_glob = (const float*)d_in[9];
    const float* b_glob = (const float*)d_in[10];

    const int* src = ei;
    const int* dstp = ei + N_EDGES;

    float* out   = (float*)d_out;
    float* out_x = out;                            // 50000 x 512
    float* out_g = out + (size_t)N_NODES * OUTW;   // 16 x 512

    const int MV_SMEM   = 131072 + 8192 + 8192;    // 147456
    const int EDGE_SMEM = 16 * 8 * 32 * 16;        // 64 KB
    const int NODE_SMEM = 131072 + 8192;           // 139264

    cudaFuncSetAttribute(matvec_mma_kernel, cudaFuncAttributeMaxDynamicSharedMemorySize, MV_SMEM);
    cudaFuncSetAttribute(edge_mma_kernel,   cudaFuncAttributeMaxDynamicSharedMemorySize, EDGE_SMEM);
    cudaFuncSetAttribute(node_mma_kernel,   cudaFuncAttributeMaxDynamicSharedMemorySize, NODE_SMEM);

    // launch order: index 3 (ncu capture point) = edge_mma_kernel
    init_kernel<<<2048, 256>>>(x, u, out_x, out_g);                          // 0
    launch_pss(matvec_mma_kernel, dim3(148), dim3(512), (size_t)MV_SMEM,     // 1 (t=0)
               out_x, W_edge, b_edge, batch);
    hist_kernel<<<1024, 256>>>(dstp, batch);                                 // 2
    launch_pss(edge_mma_kernel, dim3(296), dim3(256), (size_t)EDGE_SMEM,     // 3 PROFILED
               1, 1, ea, src, dstp, W_edge + 2 * D * D);
    finalize_counts_kernel<<<256, 256>>>();                                  // 4

    for (int t = 0; t < 3; t++) {
        const float* Xt = out_x + t * D;
        float*       Xn = out_x + (t + 1) * D;

        prep2_kernel<<<16, 128>>>(W_node, b_node);
        launch_pss(node_mma_kernel, dim3(148), dim3(512), (size_t)NODE_SMEM,
                   Xt, Xn, batch, W_node);
        global_kernel<<<16, 128>>>(W_glob, b_glob, out_g + (t + 1) * D);

        if (t < 2) {
            launch_pss(matvec_mma_kernel, dim3(148), dim3(512), (size_t)MV_SMEM,
                       Xn, W_edge, b_edge, batch);
            launch_pss(edge_mma_kernel, dim3(296), dim3(256), (size_t)EDGE_SMEM,
                       0, (t + 1) < 2 ? 1 : 0, ea, src, dstp, W_edge + 2 * D * D);
        }
    }
}